// round 1
// baseline (speedup 1.0000x reference)
#include <cuda_runtime.h>
#include <math.h>

// Problem constants (from reference setup_inputs)
#define NROWS 8192
#define FIN   128
#define FOUT  64
#define BI    64     // row tile per block
#define BJ    128    // col tile per iteration
#define PPITCH (BJ + 4)
#define NEGINF (-9e15f)

// Scratch (device globals: no allocation allowed)
__device__ float g_Wh[NROWS * FOUT];
__device__ float g_Wh1[NROWS];
__device__ float g_Wh2[NROWS];

// ---------------------------------------------------------------------------
// Kernel A: Wh = x @ W   (8192x128 @ 128x64)
// block = 256 threads handles 64 rows; W cached in smem.
// ---------------------------------------------------------------------------
__global__ __launch_bounds__(256) void wh_kernel(const float* __restrict__ x,
                                                 const float* __restrict__ W) {
    __shared__ float Ws[FIN * FOUT];
    __shared__ float xs[4][FIN];
    int tid = threadIdx.x;
    for (int idx = tid; idx < FIN * FOUT; idx += 256) Ws[idx] = W[idx];

    int f = tid & 63;
    int rsub = tid >> 6;                // 0..3
    int row0 = blockIdx.x * BI;

    for (int rr = 0; rr < BI; rr += 4) {
        __syncthreads();
        for (int idx = tid; idx < 4 * FIN; idx += 256)
            xs[idx >> 7][idx & 127] = x[(row0 + rr + (idx >> 7)) * FIN + (idx & 127)];
        __syncthreads();
        float acc = 0.f;
#pragma unroll 8
        for (int k = 0; k < FIN; k++)
            acc = fmaf(xs[rsub][k], Ws[k * FOUT + f], acc);
        g_Wh[(row0 + rr + rsub) * FOUT + f] = acc;
    }
}

// ---------------------------------------------------------------------------
// Kernel A2: Wh1 = Wh @ a[:64],  Wh2 = Wh @ a[64:]
// one warp per row.
// ---------------------------------------------------------------------------
__global__ __launch_bounds__(256) void wh12_kernel(const float* __restrict__ a) {
    int warp = threadIdx.x >> 5;
    int lane = threadIdx.x & 31;
    int row = blockIdx.x * 8 + warp;
    float v0 = g_Wh[row * FOUT + lane];
    float v1 = g_Wh[row * FOUT + 32 + lane];
    float s1 = v0 * a[lane]      + v1 * a[lane + 32];
    float s2 = v0 * a[64 + lane] + v1 * a[96 + lane];
#pragma unroll
    for (int o = 16; o > 0; o >>= 1) {
        s1 += __shfl_xor_sync(0xffffffffu, s1, o);
        s2 += __shfl_xor_sync(0xffffffffu, s2, o);
    }
    if (lane == 0) {
        g_Wh1[row] = s1;
        g_Wh2[row] = s2;
    }
}

// ---------------------------------------------------------------------------
// Kernel B: masked-softmax attention + attn @ Wh + ELU, flash-attention style.
// block = 256 threads, owns BI=64 rows; loops BJ=128 col tiles.
// ---------------------------------------------------------------------------
__global__ __launch_bounds__(256) void attn_kernel(const int* __restrict__ adj,
                                                   float* __restrict__ out) {
    extern __shared__ float sm[];
    float* P    = sm;                     // BI * PPITCH  (scores -> probs)
    float* Whs  = P + BI * PPITCH;        // BJ * FOUT
    float* wh1s = Whs + BJ * FOUT;        // BI
    float* wh2s = wh1s + BI;              // BJ
    float* m_s  = wh2s + BJ;              // BI
    float* l_s  = m_s + BI;               // BI
    float* sc_s = l_s + BI;               // BI

    int tid = threadIdx.x;
    int i0 = blockIdx.x * BI;

    if (tid < BI) {
        wh1s[tid] = g_Wh1[i0 + tid];
        m_s[tid] = -INFINITY;
        l_s[tid] = 0.f;
    }

    // phase-2 (GEMM) thread mapping: 16x16 grid, 4x4 micro-tile each
    int tr = tid >> 4;   // 0..15 -> rows tr*4 .. tr*4+3
    int tc = tid & 15;   // 0..15 -> feats tc*4 .. tc*4+3
    float acc[4][4];
#pragma unroll
    for (int i = 0; i < 4; i++)
#pragma unroll
        for (int j = 0; j < 4; j++) acc[i][j] = 0.f;

    for (int j0 = 0; j0 < NROWS; j0 += BJ) {
        __syncthreads();   // previous phase-2 done with P / Whs

        // load Wh tile (BJ x FOUT) and Wh2 tile into smem
        {
            const float4* src = (const float4*)(g_Wh + (size_t)j0 * FOUT);
            float4* dst = (float4*)Whs;
            for (int idx = tid; idx < (BJ * FOUT) / 4; idx += 256) dst[idx] = src[idx];
            if (tid < BJ) wh2s[tid] = g_Wh2[j0 + tid];
        }
        __syncthreads();

        // step 1: masked leaky scores into P (coalesced adj reads)
        for (int idx = tid; idx < BI * BJ; idx += 256) {
            int r = idx >> 7;
            int c = idx & 127;
            int av = adj[(size_t)(i0 + r) * NROWS + j0 + c];
            float ev = wh1s[r] + wh2s[c];
            ev = ev > 0.f ? ev : 0.2f * ev;
            P[r * PPITCH + c] = (av > 0) ? ev : NEGINF;
        }
        __syncthreads();

        // step 2: row max -> online rescale factors
        {
            int r = tid >> 2;
            int q = tid & 3;
            float mx = -INFINITY;
            for (int c = q; c < BJ; c += 4) mx = fmaxf(mx, P[r * PPITCH + c]);
            mx = fmaxf(mx, __shfl_xor_sync(0xffffffffu, mx, 1));
            mx = fmaxf(mx, __shfl_xor_sync(0xffffffffu, mx, 2));
            if (q == 0) {
                float mo = m_s[r];
                float mn = fmaxf(mo, mx);
                float sc = __expf(mo - mn);     // exp(-inf)=0 first tile
                sc_s[r] = sc;
                m_s[r] = mn;
                l_s[r] *= sc;
            }
        }
        __syncthreads();

        // step 3: exponentiate, accumulate l
        {
            int r = tid >> 2;
            int q = tid & 3;
            float mn = m_s[r];
            float ls = 0.f;
            for (int c = q; c < BJ; c += 4) {
                float p = __expf(P[r * PPITCH + c] - mn);
                P[r * PPITCH + c] = p;
                ls += p;
            }
            ls += __shfl_xor_sync(0xffffffffu, ls, 1);
            ls += __shfl_xor_sync(0xffffffffu, ls, 2);
            if (q == 0) l_s[r] += ls;
        }
        __syncthreads();

        // phase 2: acc = acc*scale + P(64xBJ) @ Whs(BJx64), 4x4 per thread
        {
            float s0 = sc_s[tr * 4 + 0];
            float s1 = sc_s[tr * 4 + 1];
            float s2 = sc_s[tr * 4 + 2];
            float s3 = sc_s[tr * 4 + 3];
#pragma unroll
            for (int j = 0; j < 4; j++) {
                acc[0][j] *= s0; acc[1][j] *= s1;
                acc[2][j] *= s2; acc[3][j] *= s3;
            }
            const float4* Whs4 = (const float4*)Whs;
#pragma unroll 4
            for (int c = 0; c < BJ; c++) {
                float4 wv = Whs4[c * 16 + tc];
                float p0 = P[(tr * 4 + 0) * PPITCH + c];
                float p1 = P[(tr * 4 + 1) * PPITCH + c];
                float p2 = P[(tr * 4 + 2) * PPITCH + c];
                float p3 = P[(tr * 4 + 3) * PPITCH + c];
                acc[0][0] = fmaf(p0, wv.x, acc[0][0]);
                acc[0][1] = fmaf(p0, wv.y, acc[0][1]);
                acc[0][2] = fmaf(p0, wv.z, acc[0][2]);
                acc[0][3] = fmaf(p0, wv.w, acc[0][3]);
                acc[1][0] = fmaf(p1, wv.x, acc[1][0]);
                acc[1][1] = fmaf(p1, wv.y, acc[1][1]);
                acc[1][2] = fmaf(p1, wv.z, acc[1][2]);
                acc[1][3] = fmaf(p1, wv.w, acc[1][3]);
                acc[2][0] = fmaf(p2, wv.x, acc[2][0]);
                acc[2][1] = fmaf(p2, wv.y, acc[2][1]);
                acc[2][2] = fmaf(p2, wv.z, acc[2][2]);
                acc[2][3] = fmaf(p2, wv.w, acc[2][3]);
                acc[3][0] = fmaf(p3, wv.x, acc[3][0]);
                acc[3][1] = fmaf(p3, wv.y, acc[3][1]);
                acc[3][2] = fmaf(p3, wv.z, acc[3][2]);
                acc[3][3] = fmaf(p3, wv.w, acc[3][3]);
            }
        }
    }
    __syncthreads();

    // epilogue: normalize by l, ELU, store
#pragma unroll
    for (int i = 0; i < 4; i++) {
        int r = tr * 4 + i;
        float invl = 1.f / l_s[r];
        float4 v;
        v.x = acc[i][0] * invl;
        v.y = acc[i][1] * invl;
        v.z = acc[i][2] * invl;
        v.w = acc[i][3] * invl;
        v.x = v.x > 0.f ? v.x : (__expf(v.x) - 1.f);
        v.y = v.y > 0.f ? v.y : (__expf(v.y) - 1.f);
        v.z = v.z > 0.f ? v.z : (__expf(v.z) - 1.f);
        v.w = v.w > 0.f ? v.w : (__expf(v.w) - 1.f);
        *(float4*)(out + (size_t)(i0 + r) * FOUT + tc * 4) = v;
    }
}

// ---------------------------------------------------------------------------
extern "C" void kernel_launch(void* const* d_in, const int* in_sizes, int n_in,
                              void* d_out, int out_size) {
    const float* x   = (const float*)d_in[0];   // [8192,128]
    const int*   adj = (const int*)d_in[1];     // [8192,8192]
    const float* W   = (const float*)d_in[2];   // [128,64]
    const float* a   = (const float*)d_in[3];   // [128,1]
    float* out = (float*)d_out;                 // [8192,64]

    wh_kernel<<<NROWS / BI, 256>>>(x, W);
    wh12_kernel<<<NROWS / 8, 256>>>(a);

    size_t smem = (size_t)(BI * PPITCH + BJ * FOUT + BI + BJ + 3 * BI) * sizeof(float);
    static int attr_set = 0;
    if (!attr_set) {
        cudaFuncSetAttribute(attn_kernel, cudaFuncAttributeMaxDynamicSharedMemorySize,
                             (int)smem);
        attr_set = 1;
    }
    attn_kernel<<<NROWS / BI, 256, smem>>>(adj, out);
}

// round 2
// speedup vs baseline: 1.8541x; 1.8541x over previous
#include <cuda_runtime.h>
#include <math.h>
#include <stdint.h>

#define NROWS 8192
#define FIN   128
#define FOUT  64
#define BI    64
#define BJ    128
#define PP    130          // pitch (in 8-byte pairs) of duplicated P tile
typedef unsigned long long ull;

__device__ float g_Wh[NROWS * FOUT];
__device__ float g_Wh1[NROWS];
__device__ float g_Wh2[NROWS];

// ---- f32x2 helpers (sm_103a packed fp32) ----------------------------------
__device__ __forceinline__ ull packf2(float a, float b) {
    ull r;
    asm("mov.b64 %0,{%1,%2};" : "=l"(r)
        : "r"(__float_as_uint(a)), "r"(__float_as_uint(b)));
    return r;
}
__device__ __forceinline__ void fmaf2(ull& acc, ull a, ull b) {
    asm("fma.rn.f32x2 %0,%1,%2,%0;" : "+l"(acc) : "l"(a), "l"(b));
}
__device__ __forceinline__ void unpackf2(ull v, float& lo, float& hi) {
    uint32_t l, h;
    asm("mov.b64 {%0,%1},%2;" : "=r"(l), "=r"(h) : "l"(v));
    lo = __uint_as_float(l);
    hi = __uint_as_float(h);
}

// ---------------------------------------------------------------------------
// Kernel A: Wh = x @ W   (8192x128 @ 128x64), one 64-row tile per block.
// ---------------------------------------------------------------------------
__global__ __launch_bounds__(256) void wh_kernel(const float* __restrict__ x,
                                                 const float* __restrict__ W) {
    extern __shared__ float shm[];
    float* xs = shm;                 // 64 rows x pitch 132
    float* Ws = shm + 64 * 132;      // 128 x 64
    int tid = threadIdx.x;
    int row0 = blockIdx.x * BI;

    for (int u = tid; u < 2048; u += 256) {
        int rr = u >> 5, cc = u & 31;
        float4 v = ((const float4*)(x + (size_t)(row0 + rr) * FIN))[cc];
        *(float4*)(xs + rr * 132 + cc * 4) = v;
    }
    for (int u = tid; u < 2048; u += 256)
        ((float4*)Ws)[u] = ((const float4*)W)[u];
    __syncthreads();

    int tr = tid >> 4, tc = tid & 15;
    ull acc[4][2] = {{0ull, 0ull}, {0ull, 0ull}, {0ull, 0ull}, {0ull, 0ull}};
    const ulonglong2* W2 = (const ulonglong2*)Ws;
#pragma unroll 4
    for (int k = 0; k < FIN; k++) {
        ulonglong2 wv = W2[k * 16 + tc];
#pragma unroll
        for (int i = 0; i < 4; i++) {
            float xv = xs[(tr * 4 + i) * 132 + k];
            ull xp = packf2(xv, xv);
            fmaf2(acc[i][0], xp, wv.x);
            fmaf2(acc[i][1], xp, wv.y);
        }
    }
#pragma unroll
    for (int i = 0; i < 4; i++) {
        float o0, o1, o2, o3;
        unpackf2(acc[i][0], o0, o1);
        unpackf2(acc[i][1], o2, o3);
        *(float4*)(g_Wh + (size_t)(row0 + tr * 4 + i) * FOUT + tc * 4) =
            make_float4(o0, o1, o2, o3);
    }
}

// ---------------------------------------------------------------------------
// Kernel A2: Wh1 = Wh @ a[:64],  Wh2 = Wh @ a[64:]   (one warp per row)
// ---------------------------------------------------------------------------
__global__ __launch_bounds__(256) void wh12_kernel(const float* __restrict__ a) {
    int warp = threadIdx.x >> 5;
    int lane = threadIdx.x & 31;
    int row = blockIdx.x * 8 + warp;
    float v0 = g_Wh[row * FOUT + lane];
    float v1 = g_Wh[row * FOUT + 32 + lane];
    float s1 = v0 * a[lane] + v1 * a[lane + 32];
    float s2 = v0 * a[64 + lane] + v1 * a[96 + lane];
#pragma unroll
    for (int o = 16; o > 0; o >>= 1) {
        s1 += __shfl_xor_sync(0xffffffffu, s1, o);
        s2 += __shfl_xor_sync(0xffffffffu, s2, o);
    }
    if (lane == 0) {
        g_Wh1[row] = s1;
        g_Wh2[row] = s2;
    }
}

// ---------------------------------------------------------------------------
// Kernel B: masked attention (no max-subtraction softmax) + attn @ Wh + ELU.
// block = 256 threads owns 64 rows; loops over 128-col tiles.
// ---------------------------------------------------------------------------
__global__ __launch_bounds__(256) void attn_kernel(const int* __restrict__ adj,
                                                   float* __restrict__ out) {
    extern __shared__ char smraw[];
    ull* P2      = (ull*)smraw;                          // 64*PP pairs (p,p) = 66560 B
    float* Whs0  = (float*)(smraw + 64 * PP * 8);        // 128*64 = 32768 B
    float* Whs1  = Whs0 + BJ * FOUT;                     // 32768 B
    float* wh2s  = Whs1 + BJ * FOUT;                     // 128 floats
    float* lpart = wh2s + BJ;                            // 256 floats

    int tid = threadIdx.x;
    int i0 = blockIdx.x * BI;

    // phase-1 mapping: row r, col-slot q (4 threads per row)
    int r = tid >> 2, q = tid & 3;
    const int4* arow = (const int4*)adj + (size_t)(i0 + r) * (NROWS / 4) + q;
    float wh1r = g_Wh1[i0 + r];
    float lsum = 0.f;

    // phase-2 mapping: 16x16, each thread 4 rows x 4 feats (2 f32x2 pairs)
    int tr = tid >> 4, tc = tid & 15;
    ull acc[4][2] = {{0ull, 0ull}, {0ull, 0ull}, {0ull, 0ull}, {0ull, 0ull}};

    uint32_t s_whs0 = (uint32_t)__cvta_generic_to_shared(Whs0);
    uint32_t s_whs1 = (uint32_t)__cvta_generic_to_shared(Whs1);

    // ---- prologue: prefetch tile 0 ----
    int4 pre[8];
#pragma unroll
    for (int k = 0; k < 8; k++) pre[k] = arow[4 * k];
    float wh2pre = 0.f;
    if (tid < BJ) wh2pre = g_Wh2[tid];
#pragma unroll
    for (int u = 0; u < 8; u++) {
        uint32_t d = s_whs0 + (uint32_t)(tid + 256 * u) * 16;
        const float* s = g_Wh + (size_t)(tid + 256 * u) * 4;
        asm volatile("cp.async.cg.shared.global [%0],[%1],16;" :: "r"(d), "l"(s));
    }
    asm volatile("cp.async.commit_group;" ::: "memory");

    for (int t = 0; t < NROWS / BJ; ++t) {
        int j0 = t << 7;
        int j0n = (j0 + BJ) & (NROWS - 1);

        __syncthreads();                       // A: prev phase-2 done with P2/Whs
        if (tid < BJ) wh2s[tid] = wh2pre;
        __syncthreads();                       // B: wh2s visible

        // ---- phase 1: P(r,c) = adj ? exp(leaky(wh1+wh2)) : 0, duplicated ----
#pragma unroll
        for (int k = 0; k < 8; k++) {
            int4 a4 = pre[k];
            int c0 = (q << 2) + (k << 4);
            float z0 = wh1r + wh2s[c0 + 0];
            float z1 = wh1r + wh2s[c0 + 1];
            float z2 = wh1r + wh2s[c0 + 2];
            float z3 = wh1r + wh2s[c0 + 3];
            z0 = fmaxf(z0, 0.2f * z0);
            z1 = fmaxf(z1, 0.2f * z1);
            z2 = fmaxf(z2, 0.2f * z2);
            z3 = fmaxf(z3, 0.2f * z3);
            float p0 = (a4.x != 0) ? __expf(z0) : 0.f;
            float p1 = (a4.y != 0) ? __expf(z1) : 0.f;
            float p2 = (a4.z != 0) ? __expf(z2) : 0.f;
            float p3 = (a4.w != 0) ? __expf(z3) : 0.f;
            lsum += (p0 + p1) + (p2 + p3);
            ulonglong2* dst = (ulonglong2*)(P2 + (size_t)r * PP + c0);
            dst[0] = make_ulonglong2(packf2(p0, p0), packf2(p1, p1));
            dst[1] = make_ulonglong2(packf2(p2, p2), packf2(p3, p3));
        }

        // ---- prefetch next tile (hidden under phase 2) ----
#pragma unroll
        for (int k = 0; k < 8; k++) pre[k] = arow[(j0n >> 2) + 4 * k];
        if (tid < BJ) wh2pre = g_Wh2[j0n + tid];
        {
            uint32_t d0 = (t & 1) ? s_whs0 : s_whs1;  // next buffer
            const float* src = g_Wh + (size_t)j0n * FOUT;
#pragma unroll
            for (int u = 0; u < 8; u++) {
                uint32_t d = d0 + (uint32_t)(tid + 256 * u) * 16;
                const float* s = src + (size_t)(tid + 256 * u) * 4;
                asm volatile("cp.async.cg.shared.global [%0],[%1],16;" :: "r"(d), "l"(s));
            }
            asm volatile("cp.async.commit_group;" ::: "memory");
        }
        asm volatile("cp.async.wait_group 1;" ::: "memory");  // current Whs ready
        __syncthreads();                       // C: P2 + Whs visible

        // ---- phase 2: acc += P(64xBJ) @ Whs(BJx64), f32x2 packed ----
        const ulonglong2* W2 = (const ulonglong2*)((t & 1) ? Whs1 : Whs0);
        const ull* Pr0 = P2 + (size_t)(tr * 4) * PP;
#pragma unroll 8
        for (int c = 0; c < BJ; c++) {
            ulonglong2 wv = W2[c * 16 + tc];
            ull p0 = Pr0[c];
            ull p1 = Pr0[PP + c];
            ull p2 = Pr0[2 * PP + c];
            ull p3 = Pr0[3 * PP + c];
            fmaf2(acc[0][0], p0, wv.x); fmaf2(acc[0][1], p0, wv.y);
            fmaf2(acc[1][0], p1, wv.x); fmaf2(acc[1][1], p1, wv.y);
            fmaf2(acc[2][0], p2, wv.x); fmaf2(acc[2][1], p2, wv.y);
            fmaf2(acc[3][0], p3, wv.x); fmaf2(acc[3][1], p3, wv.y);
        }
    }

    // ---- epilogue: reduce l, normalize, ELU, store ----
    __syncthreads();
    lpart[tid] = lsum;          // lpart[r*4+q] == lpart[tid]
    __syncthreads();
#pragma unroll
    for (int i = 0; i < 4; i++) {
        int row = tr * 4 + i;
        float l = (lpart[row * 4 + 0] + lpart[row * 4 + 1]) +
                  (lpart[row * 4 + 2] + lpart[row * 4 + 3]);
        float invl = 1.0f / l;
        float o0, o1, o2, o3;
        unpackf2(acc[i][0], o0, o1);
        unpackf2(acc[i][1], o2, o3);
        o0 *= invl; o1 *= invl; o2 *= invl; o3 *= invl;
        o0 = o0 > 0.f ? o0 : (__expf(o0) - 1.f);
        o1 = o1 > 0.f ? o1 : (__expf(o1) - 1.f);
        o2 = o2 > 0.f ? o2 : (__expf(o2) - 1.f);
        o3 = o3 > 0.f ? o3 : (__expf(o3) - 1.f);
        *(float4*)(out + (size_t)(i0 + row) * FOUT + tc * 4) =
            make_float4(o0, o1, o2, o3);
    }
}

// ---------------------------------------------------------------------------
extern "C" void kernel_launch(void* const* d_in, const int* in_sizes, int n_in,
                              void* d_out, int out_size) {
    const float* x   = (const float*)d_in[0];   // [8192,128]
    const int*   adj = (const int*)d_in[1];     // [8192,8192]
    const float* W   = (const float*)d_in[2];   // [128,64]
    const float* a   = (const float*)d_in[3];   // [128,1]
    float* out = (float*)d_out;                 // [8192,64]

    size_t smem_wh = (size_t)(64 * 132 + 128 * 64) * sizeof(float);
    size_t smem_at = (size_t)64 * PP * 8 + (size_t)2 * BJ * FOUT * 4 +
                     (size_t)(BJ + 256) * 4;
    static int attr_set = 0;
    if (!attr_set) {
        cudaFuncSetAttribute(wh_kernel, cudaFuncAttributeMaxDynamicSharedMemorySize,
                             (int)smem_wh);
        cudaFuncSetAttribute(attn_kernel, cudaFuncAttributeMaxDynamicSharedMemorySize,
                             (int)smem_at);
        attr_set = 1;
    }

    wh_kernel<<<NROWS / BI, 256, smem_wh>>>(x, W);
    wh12_kernel<<<NROWS / 8, 256>>>(a);
    attn_kernel<<<NROWS / BI, 256, smem_at>>>(adj, out);
}

// round 3
// speedup vs baseline: 2.3961x; 1.2923x over previous
#include <cuda_runtime.h>
#include <math.h>
#include <stdint.h>

#define NROWS 8192
#define FIN   128
#define FOUT  64
#define BI    64
#define BJ    128
#define PPF   129          // P pitch in floats: 8*129 % 32 == 8 -> conflict-free
typedef unsigned long long ull;

__device__ float g_Wh[NROWS * FOUT];
__device__ float g_Wh1[NROWS];
__device__ float g_Wh2[NROWS];

// ---- f32x2 helpers (sm_103a packed fp32) ----------------------------------
__device__ __forceinline__ ull packf2(float a, float b) {
    ull r;
    asm("mov.b64 %0,{%1,%2};" : "=l"(r)
        : "r"(__float_as_uint(a)), "r"(__float_as_uint(b)));
    return r;
}
__device__ __forceinline__ void fmaf2(ull& acc, ull a, ull b) {
    asm("fma.rn.f32x2 %0,%1,%2,%0;" : "+l"(acc) : "l"(a), "l"(b));
}
__device__ __forceinline__ void unpackf2(ull v, float& lo, float& hi) {
    uint32_t l, h;
    asm("mov.b64 {%0,%1},%2;" : "=r"(l), "=r"(h) : "l"(v));
    lo = __uint_as_float(l);
    hi = __uint_as_float(h);
}

// ---------------------------------------------------------------------------
// Kernel A: Wh = x @ W   (8192x128 @ 128x64)
// ---------------------------------------------------------------------------
__global__ __launch_bounds__(256) void wh_kernel(const float* __restrict__ x,
                                                 const float* __restrict__ W) {
    extern __shared__ float shm[];
    float* xs = shm;                 // 64 rows x pitch 132
    float* Ws = shm + 64 * 132;      // 128 x 64
    int tid = threadIdx.x;
    int row0 = blockIdx.x * BI;

    for (int u = tid; u < 2048; u += 256) {
        int rr = u >> 5, cc = u & 31;
        float4 v = ((const float4*)(x + (size_t)(row0 + rr) * FIN))[cc];
        *(float4*)(xs + rr * 132 + cc * 4) = v;
    }
    for (int u = tid; u < 2048; u += 256)
        ((float4*)Ws)[u] = ((const float4*)W)[u];
    __syncthreads();

    int tr = tid >> 4, tc = tid & 15;
    ull acc[4][2] = {{0ull, 0ull}, {0ull, 0ull}, {0ull, 0ull}, {0ull, 0ull}};
    const ulonglong2* W2 = (const ulonglong2*)Ws;
#pragma unroll 4
    for (int k = 0; k < FIN; k++) {
        ulonglong2 wv = W2[k * 16 + tc];
#pragma unroll
        for (int i = 0; i < 4; i++) {
            float xv = xs[(tr * 4 + i) * 132 + k];
            ull xp = packf2(xv, xv);
            fmaf2(acc[i][0], xp, wv.x);
            fmaf2(acc[i][1], xp, wv.y);
        }
    }
#pragma unroll
    for (int i = 0; i < 4; i++) {
        float o0, o1, o2, o3;
        unpackf2(acc[i][0], o0, o1);
        unpackf2(acc[i][1], o2, o3);
        *(float4*)(g_Wh + (size_t)(row0 + tr * 4 + i) * FOUT + tc * 4) =
            make_float4(o0, o1, o2, o3);
    }
}

// ---------------------------------------------------------------------------
// Kernel A2: Wh1 = Wh @ a[:64],  Wh2 = Wh @ a[64:]
// ---------------------------------------------------------------------------
__global__ __launch_bounds__(256) void wh12_kernel(const float* __restrict__ a) {
    int warp = threadIdx.x >> 5;
    int lane = threadIdx.x & 31;
    int row = blockIdx.x * 8 + warp;
    float v0 = g_Wh[row * FOUT + lane];
    float v1 = g_Wh[row * FOUT + 32 + lane];
    float s1 = v0 * a[lane] + v1 * a[lane + 32];
    float s2 = v0 * a[64 + lane] + v1 * a[96 + lane];
#pragma unroll
    for (int o = 16; o > 0; o >>= 1) {
        s1 += __shfl_xor_sync(0xffffffffu, s1, o);
        s2 += __shfl_xor_sync(0xffffffffu, s2, o);
    }
    if (lane == 0) {
        g_Wh1[row] = s1;
        g_Wh2[row] = s2;
    }
}

// ---------------------------------------------------------------------------
// Kernel B: masked attention + attn @ Wh + ELU.
// 256 threads = 4 K-split groups x (8x8 threads), micro-tile 8 rows x 8 feats.
// ---------------------------------------------------------------------------
__global__ __launch_bounds__(256, 1) void attn_kernel(const int* __restrict__ adj,
                                                      float* __restrict__ out) {
    extern __shared__ float sm[];
    float* Pf    = sm;                    // 64 * PPF floats (scores/probs)
    float* Whs0  = sm + 64 * PPF;         // 128*64
    float* Whs1  = Whs0 + BJ * FOUT;      // 128*64
    float* wh2s  = Whs1 + BJ * FOUT;      // 128
    float* lred  = wh2s + BJ;             // 256

    int tid = threadIdx.x;
    int i0 = blockIdx.x * BI;

    // ---- phase-1 mapping: row r (one per thread), col-slot q ----
    int r = tid >> 2, q = tid & 3;
    const int4* arow = (const int4*)adj + (size_t)(i0 + r) * (NROWS / 4) + q;
    float wh1r = g_Wh1[i0 + r];
    float lsum = 0.f;

    // ---- phase-2 mapping: group g (K-split), 8x8 thread grid ----
    int g = tid >> 6;          // 0..3 -> c in [g*32, g*32+32)
    int w = tid & 63;
    int tr = w >> 3;           // rows tr*8 .. tr*8+7
    int tcq = w & 7;           // feat pairs at f = 2*tcq + 16k, k=0..3
    ull acc[8][4];
#pragma unroll
    for (int i = 0; i < 8; i++)
#pragma unroll
        for (int k = 0; k < 4; k++) acc[i][k] = 0ull;

    uint32_t s_whs0 = (uint32_t)__cvta_generic_to_shared(Whs0);
    uint32_t s_whs1 = (uint32_t)__cvta_generic_to_shared(Whs1);

    // ---- prologue: prefetch tile 0 ----
    int4 pre[8];
#pragma unroll
    for (int k = 0; k < 8; k++) pre[k] = arow[4 * k];
    float wh2pre = 0.f;
    if (tid < BJ) wh2pre = g_Wh2[tid];
#pragma unroll
    for (int u = 0; u < 8; u++) {
        uint32_t d = s_whs0 + (uint32_t)(tid + 256 * u) * 16;
        const float* s = g_Wh + (size_t)(tid + 256 * u) * 4;
        asm volatile("cp.async.cg.shared.global [%0],[%1],16;" :: "r"(d), "l"(s));
    }
    asm volatile("cp.async.commit_group;" ::: "memory");

    for (int t = 0; t < NROWS / BJ; ++t) {
        int j0n = ((t + 1) << 7) & (NROWS - 1);

        __syncthreads();                  // A: prev phase-2 done with Pf/wh2s
        if (tid < BJ) wh2s[tid] = wh2pre;
        __syncthreads();                  // B: wh2s visible

        // ---- phase 1: P(r,c) = adj ? exp(leaky(wh1+wh2)) : 0 (scalar) ----
#pragma unroll
        for (int k = 0; k < 8; k++) {
            int4 a4 = pre[k];
            int c0 = (q << 2) + (k << 4);
            float z0 = wh1r + wh2s[c0 + 0];
            float z1 = wh1r + wh2s[c0 + 1];
            float z2 = wh1r + wh2s[c0 + 2];
            float z3 = wh1r + wh2s[c0 + 3];
            z0 = fmaxf(z0, 0.2f * z0);
            z1 = fmaxf(z1, 0.2f * z1);
            z2 = fmaxf(z2, 0.2f * z2);
            z3 = fmaxf(z3, 0.2f * z3);
            float p0 = (a4.x != 0) ? __expf(z0) : 0.f;
            float p1 = (a4.y != 0) ? __expf(z1) : 0.f;
            float p2 = (a4.z != 0) ? __expf(z2) : 0.f;
            float p3 = (a4.w != 0) ? __expf(z3) : 0.f;
            lsum += (p0 + p1) + (p2 + p3);
            float* dst = Pf + (size_t)r * PPF + c0;
            dst[0] = p0; dst[1] = p1; dst[2] = p2; dst[3] = p3;
        }

        // ---- prefetch next tile (hidden under phase 2) ----
#pragma unroll
        for (int k = 0; k < 8; k++) pre[k] = arow[(j0n >> 2) + 4 * k];
        if (tid < BJ) wh2pre = g_Wh2[j0n + tid];
        {
            uint32_t d0 = (t & 1) ? s_whs0 : s_whs1;
            const float* src = g_Wh + (size_t)j0n * FOUT;
#pragma unroll
            for (int u = 0; u < 8; u++) {
                uint32_t d = d0 + (uint32_t)(tid + 256 * u) * 16;
                const float* s = src + (size_t)(tid + 256 * u) * 4;
                asm volatile("cp.async.cg.shared.global [%0],[%1],16;" :: "r"(d), "l"(s));
            }
            asm volatile("cp.async.commit_group;" ::: "memory");
        }
        asm volatile("cp.async.wait_group 1;" ::: "memory");
        __syncthreads();                  // C: Pf + current Whs visible

        // ---- phase 2: acc += P[64 x 32(g)] @ Whs[32(g) x 64] ----
        const float* Ws = (t & 1) ? Whs1 : Whs0;
        const float* prow = Pf + tr * 8 * PPF + g * 32;
#pragma unroll 4
        for (int cc = 0; cc < 32; cc++) {
            const ull* wr = (const ull*)(Ws + (g * 32 + cc) * FOUT);
            ull w0 = wr[tcq];
            ull w1 = wr[tcq + 8];
            ull w2 = wr[tcq + 16];
            ull w3 = wr[tcq + 24];
#pragma unroll
            for (int i = 0; i < 8; i++) {
                float p = prow[i * PPF + cc];
                ull pp = packf2(p, p);
                fmaf2(acc[i][0], pp, w0);
                fmaf2(acc[i][1], pp, w1);
                fmaf2(acc[i][2], pp, w2);
                fmaf2(acc[i][3], pp, w3);
            }
        }
    }

    // ---- epilogue ----
    __syncthreads();
    lred[tid] = lsum;
    __syncthreads();

    float* Out = Pf;  // reuse P region: 64x64, pitch 64
#pragma unroll
    for (int gg = 0; gg < 4; gg++) {
        if (g == gg) {
#pragma unroll
            for (int i = 0; i < 8; i++) {
                float* orow = Out + (tr * 8 + i) * FOUT;
#pragma unroll
                for (int k = 0; k < 4; k++) {
                    float lo, hi;
                    unpackf2(acc[i][k], lo, hi);
                    int f = 2 * tcq + 16 * k;
                    if (gg == 0) {
                        orow[f] = lo;
                        orow[f + 1] = hi;
                    } else {
                        orow[f] += lo;
                        orow[f + 1] += hi;
                    }
                }
            }
        }
        __syncthreads();
    }

    for (int idx = tid; idx < (BI * FOUT) / 4; idx += 256) {
        int row = idx >> 4;
        int fc = idx & 15;
        float l = (lred[row * 4 + 0] + lred[row * 4 + 1]) +
                  (lred[row * 4 + 2] + lred[row * 4 + 3]);
        float invl = 1.0f / l;
        float4 v = *(float4*)(Out + row * FOUT + fc * 4);
        v.x *= invl; v.y *= invl; v.z *= invl; v.w *= invl;
        v.x = v.x > 0.f ? v.x : (__expf(v.x) - 1.f);
        v.y = v.y > 0.f ? v.y : (__expf(v.y) - 1.f);
        v.z = v.z > 0.f ? v.z : (__expf(v.z) - 1.f);
        v.w = v.w > 0.f ? v.w : (__expf(v.w) - 1.f);
        *(float4*)(out + (size_t)(i0 + row) * FOUT + fc * 4) = v;
    }
}

// ---------------------------------------------------------------------------
extern "C" void kernel_launch(void* const* d_in, const int* in_sizes, int n_in,
                              void* d_out, int out_size) {
    const float* x   = (const float*)d_in[0];   // [8192,128]
    const int*   adj = (const int*)d_in[1];     // [8192,8192]
    const float* W   = (const float*)d_in[2];   // [128,64]
    const float* a   = (const float*)d_in[3];   // [128,1]
    float* out = (float*)d_out;                 // [8192,64]

    size_t smem_wh = (size_t)(64 * 132 + 128 * 64) * sizeof(float);
    size_t smem_at = (size_t)(64 * PPF + 2 * BJ * FOUT + BJ + 256) * sizeof(float);
    static int attr_set = 0;
    if (!attr_set) {
        cudaFuncSetAttribute(wh_kernel, cudaFuncAttributeMaxDynamicSharedMemorySize,
                             (int)smem_wh);
        cudaFuncSetAttribute(attn_kernel, cudaFuncAttributeMaxDynamicSharedMemorySize,
                             (int)smem_at);
        attr_set = 1;
    }

    wh_kernel<<<NROWS / BI, 256, smem_wh>>>(x, W);
    wh12_kernel<<<NROWS / 8, 256>>>(a);
    attn_kernel<<<NROWS / BI, 256, smem_at>>>(adj, out);
}

// round 5
// speedup vs baseline: 3.8157x; 1.5925x over previous
#include <cuda_runtime.h>
#include <cuda_bf16.h>
#include <math.h>
#include <stdint.h>

#define NROWS 8192
#define FIN   128
#define FOUT  64
#define BI    64
#define BJ    128
#define TILES (NROWS / BJ)       // 64
#define L2E 1.4426950408889634f
#define PB  272                  // P / WhT smem row pitch in BYTES (136 bf16)

// attn smem map (bytes)
#define SM_PHI 0
#define SM_PLO 17408
#define SM_WH  34816             // + buf*34816 + plane*17408
#define SM_W2  104448            // float[128]
#define SM_LR  105472            // float[256]
#define SM_TOTB 106496

typedef unsigned long long ull;

__device__ float g_Wh[NROWS * FOUT];
__device__ float g_Wh1[NROWS];
__device__ float g_Wh2[NROWS];
__device__ __nv_bfloat16 g_WhT_hi[FOUT * NROWS];
__device__ __nv_bfloat16 g_WhT_lo[FOUT * NROWS];

// ---- helpers ----------------------------------------------------------------
__device__ __forceinline__ uint32_t s2u(const void* p) {
    uint32_t a;
    asm("{.reg .u64 t; cvta.to.shared.u64 t,%1; cvt.u32.u64 %0,t;}" : "=r"(a) : "l"(p));
    return a;
}
__device__ __forceinline__ float ex2f(float x) {
    float y; asm("ex2.approx.ftz.f32 %0,%1;" : "=f"(y) : "f"(x)); return y;
}
// packed bf16x2: lo half = a, hi half = b
__device__ __forceinline__ uint32_t bf2(float a, float b) {
    uint32_t r; asm("cvt.rn.bf16x2.f32 %0,%2,%1;" : "=r"(r) : "f"(a), "f"(b)); return r;
}
__device__ __forceinline__ void cpasync16(uint32_t d, const void* s) {
    asm volatile("cp.async.cg.shared.global [%0],[%1],16;" :: "r"(d), "l"(s));
}
__device__ __forceinline__ void ldsm4(uint32_t* r, uint32_t a) {
    asm volatile("ldmatrix.sync.aligned.m8n8.x4.shared.b16 {%0,%1,%2,%3},[%4];"
                 : "=r"(r[0]), "=r"(r[1]), "=r"(r[2]), "=r"(r[3]) : "r"(a));
}
__device__ __forceinline__ void mmabf(float* d, const uint32_t* a, const uint32_t* b) {
    asm volatile("mma.sync.aligned.m16n8k16.row.col.f32.bf16.bf16.f32 "
                 "{%0,%1,%2,%3},{%4,%5,%6,%7},{%8,%9},{%0,%1,%2,%3};"
                 : "+f"(d[0]), "+f"(d[1]), "+f"(d[2]), "+f"(d[3])
                 : "r"(a[0]), "r"(a[1]), "r"(a[2]), "r"(a[3]), "r"(b[0]), "r"(b[1]));
}
__device__ __forceinline__ ull packf2(float a, float b) {
    ull r;
    asm("mov.b64 %0,{%1,%2};" : "=l"(r) : "r"(__float_as_uint(a)), "r"(__float_as_uint(b)));
    return r;
}
__device__ __forceinline__ void fmaf2(ull& acc, ull a, ull b) {
    asm("fma.rn.f32x2 %0,%1,%2,%0;" : "+l"(acc) : "l"(a), "l"(b));
}
__device__ __forceinline__ void unpackf2(ull v, float& lo, float& hi) {
    uint32_t l, h;
    asm("mov.b64 {%0,%1},%2;" : "=r"(l), "=r"(h) : "l"(v));
    lo = __uint_as_float(l); hi = __uint_as_float(h);
}

// ---------------------------------------------------------------------------
// Kernel A: Wh = x @ W   (32 rows per block, grid 256)
// ---------------------------------------------------------------------------
__global__ __launch_bounds__(256) void wh_kernel(const float* __restrict__ x,
                                                 const float* __restrict__ W) {
    extern __shared__ float shm[];
    float* xs = shm;                 // 32 x 132
    float* Ws = shm + 32 * 132;      // 128 x 64
    int tid = threadIdx.x;
    int row0 = blockIdx.x * 32;

    for (int u = tid; u < 1024; u += 256) {
        int rr = u >> 5, cc = u & 31;
        float4 v = ((const float4*)(x + (size_t)(row0 + rr) * FIN))[cc];
        *(float4*)(xs + rr * 132 + cc * 4) = v;
    }
    for (int u = tid; u < 2048; u += 256)
        ((float4*)Ws)[u] = ((const float4*)W)[u];
    __syncthreads();

    int tr = tid >> 4, tc = tid & 15;
    ull acc[2][2] = {{0ull, 0ull}, {0ull, 0ull}};
    const ulonglong2* W2 = (const ulonglong2*)Ws;
#pragma unroll 4
    for (int k = 0; k < FIN; k++) {
        ulonglong2 wv = W2[k * 16 + tc];
#pragma unroll
        for (int i = 0; i < 2; i++) {
            float xv = xs[(tr * 2 + i) * 132 + k];
            ull xp = packf2(xv, xv);
            fmaf2(acc[i][0], xp, wv.x);
            fmaf2(acc[i][1], xp, wv.y);
        }
    }
#pragma unroll
    for (int i = 0; i < 2; i++) {
        float o0, o1, o2, o3;
        unpackf2(acc[i][0], o0, o1);
        unpackf2(acc[i][1], o2, o3);
        *(float4*)(g_Wh + (size_t)(row0 + tr * 2 + i) * FOUT + tc * 4) =
            make_float4(o0, o1, o2, o3);
    }
}

// ---------------------------------------------------------------------------
// Kernel A2: Wh1 / Wh2
// ---------------------------------------------------------------------------
__global__ __launch_bounds__(256) void wh12_kernel(const float* __restrict__ a) {
    int warp = threadIdx.x >> 5;
    int lane = threadIdx.x & 31;
    int row = blockIdx.x * 8 + warp;
    float v0 = g_Wh[row * FOUT + lane];
    float v1 = g_Wh[row * FOUT + 32 + lane];
    float s1 = v0 * a[lane] + v1 * a[lane + 32];
    float s2 = v0 * a[64 + lane] + v1 * a[96 + lane];
#pragma unroll
    for (int o = 16; o > 0; o >>= 1) {
        s1 += __shfl_xor_sync(0xffffffffu, s1, o);
        s2 += __shfl_xor_sync(0xffffffffu, s2, o);
    }
    if (lane == 0) { g_Wh1[row] = s1; g_Wh2[row] = s2; }
}

// ---------------------------------------------------------------------------
// Transpose + bf16 hi/lo split: WhT[f][j] = Wh[j][f]
// ---------------------------------------------------------------------------
__global__ __launch_bounds__(256) void tp_kernel() {
    __shared__ float s[64][129];
    int b = blockIdx.x;
    int tid = threadIdx.x;
    for (int idx = tid; idx < 128 * 64; idx += 256) {
        int r = idx >> 6, f = idx & 63;
        s[f][r] = g_Wh[(size_t)(b * 128 + r) * FOUT + f];
    }
    __syncthreads();
    for (int idx = tid; idx < 64 * 128; idx += 256) {
        int f = idx >> 7, r = idx & 127;
        float v = s[f][r];
        __nv_bfloat16 h = __float2bfloat16(v);
        float hf = __bfloat162float(h);
        size_t o = (size_t)f * NROWS + b * 128 + r;
        g_WhT_hi[o] = h;
        g_WhT_lo[o] = __float2bfloat16(v - hf);
    }
}

// ---------------------------------------------------------------------------
// Kernel B: masked attention + attn @ Wh + ELU.
// Phase 1 SIMT -> P_hi/P_lo bf16 smem; phase 2 HMMA (bf16x3 emulated fp32).
// ---------------------------------------------------------------------------
__global__ __launch_bounds__(256, 1) void attn_kernel(const int* __restrict__ adj,
                                                      float* __restrict__ out) {
    extern __shared__ char smc[];
    uint32_t smb = s2u(smc);
    float* wh2s = (float*)(smc + SM_W2);
    float* lred = (float*)(smc + SM_LR);

    int tid = threadIdx.x;
    int i0 = blockIdx.x * BI;

    // ---- phase-1 mapping ----
    int r = tid >> 2, q = tid & 3;
    const int4* arow = (const int4*)adj + (size_t)(i0 + r) * (NROWS / 4) + q;
    float wh1r = g_Wh1[i0 + r];
    float lsum = 0.f;
    char* pst_hi = smc + SM_PHI + r * PB + q * 8;
    char* pst_lo = smc + SM_PLO + r * PB + q * 8;

    // ---- mma mapping: 8 warps = 4 m16-strips x 2 n32-halves ----
    int warp = tid >> 5, lane = tid & 31;
    int s = warp >> 1, h = warp & 1;
    uint32_t aoff = (uint32_t)(((lane & 7) + 8 * ((lane >> 3) & 1)) * PB + (lane >> 4) * 16);
    uint32_t aHi = smb + SM_PHI + s * 16 * PB + aoff;
    uint32_t aLo = aHi + (SM_PLO - SM_PHI);
    uint32_t boff = (uint32_t)(((lane & 7) + 8 * (lane >> 4)) * PB + ((lane >> 3) & 1) * 16);
    uint32_t bBase0 = smb + SM_WH + h * 32 * PB + boff;
    float acc[4][4];
#pragma unroll
    for (int i = 0; i < 4; i++)
#pragma unroll
        for (int j = 0; j < 4; j++) acc[i][j] = 0.f;

    // ---- cp.async geometry (tile-invariant): 4 chunks/thread/plane ----
    uint32_t dsto[4], srco[4];
#pragma unroll
    for (int u = 0; u < 4; u++) {
        int idx = u * 256 + tid;
        int row = idx >> 4, ch = idx & 15;
        dsto[u] = (uint32_t)(row * PB + ch * 16);
        srco[u] = (uint32_t)((row * NROWS + ch * 8) * 2);
    }

    // ---- prologue ----
    float wh2pre = (tid < BJ) ? g_Wh2[tid] : 0.f;
    int4 cur[8], nxt[8];
#pragma unroll
    for (int k = 0; k < 8; k++) cur[k] = arow[4 * k];
    {
        const char* ph = (const char*)g_WhT_hi;
        const char* pl = (const char*)g_WhT_lo;
        uint32_t b0 = smb + SM_WH;
#pragma unroll
        for (int u = 0; u < 4; u++) cpasync16(b0 + dsto[u], ph + srco[u]);
#pragma unroll
        for (int u = 0; u < 4; u++) cpasync16(b0 + 17408 + dsto[u], pl + srco[u]);
        asm volatile("cp.async.commit_group;" ::: "memory");
    }

    const float NEGI = __int_as_float(0xff800000);

    for (int t = 0; t < TILES; ++t) {
        int jn = ((t + 1) & (TILES - 1)) << 7;

        __syncthreads();                 // A: prev mma done with P / wh2s
        if (tid < BJ) wh2s[tid] = wh2pre;
        __syncthreads();                 // B: wh2s visible

        // prefetch next-tile adj + wh2
#pragma unroll
        for (int k = 0; k < 8; k++) nxt[k] = arow[(jn >> 2) + 4 * k];
        if (tid < BJ) wh2pre = g_Wh2[jn + tid];

        // ---- phase 1 ----
#pragma unroll
        for (int k = 0; k < 8; k++) {
            int4 a4 = cur[k];
            int c0 = (q << 2) + (k << 4);
            float4 wv = *(const float4*)(wh2s + c0);
            float z, u1, u2, tt, p0, p1, p2, p3;
            z = wh1r + wv.x; u1 = z * L2E; u2 = z * (0.2f * L2E);
            tt = fmaxf(u1, u2); if (a4.x == 0) tt = NEGI; p0 = ex2f(tt);
            z = wh1r + wv.y; u1 = z * L2E; u2 = z * (0.2f * L2E);
            tt = fmaxf(u1, u2); if (a4.y == 0) tt = NEGI; p1 = ex2f(tt);
            z = wh1r + wv.z; u1 = z * L2E; u2 = z * (0.2f * L2E);
            tt = fmaxf(u1, u2); if (a4.z == 0) tt = NEGI; p2 = ex2f(tt);
            z = wh1r + wv.w; u1 = z * L2E; u2 = z * (0.2f * L2E);
            tt = fmaxf(u1, u2); if (a4.w == 0) tt = NEGI; p3 = ex2f(tt);
            lsum += (p0 + p1) + (p2 + p3);
            uint32_t h0 = bf2(p0, p1);
            uint32_t h1 = bf2(p2, p3);
            float r0 = p0 - __uint_as_float(h0 << 16);
            float r1 = p1 - __uint_as_float(h0 & 0xffff0000u);
            float r2 = p2 - __uint_as_float(h1 << 16);
            float r3 = p3 - __uint_as_float(h1 & 0xffff0000u);
            *(uint2*)(pst_hi + k * 32) = make_uint2(h0, h1);
            *(uint2*)(pst_lo + k * 32) = make_uint2(bf2(r0, r1), bf2(r2, r3));
        }
#pragma unroll
        for (int k = 0; k < 8; k++) cur[k] = nxt[k];

        // ---- prefetch Wh(t+1) ----
        {
            uint32_t b0 = smb + SM_WH + ((t + 1) & 1) * 34816;
            const char* ph = (const char*)g_WhT_hi;
            const char* pl = (const char*)g_WhT_lo;
            uint32_t j2 = (uint32_t)jn * 2;
#pragma unroll
            for (int u = 0; u < 4; u++) cpasync16(b0 + dsto[u], ph + srco[u] + j2);
#pragma unroll
            for (int u = 0; u < 4; u++) cpasync16(b0 + 17408 + dsto[u], pl + srco[u] + j2);
            asm volatile("cp.async.commit_group;" ::: "memory");
        }
        asm volatile("cp.async.wait_group 1;" ::: "memory");
        __syncthreads();                 // C: P + current Wh visible

        // ---- phase 2: HMMA ----
        uint32_t whi = bBase0 + (t & 1) * 34816;
        uint32_t wlo = whi + 17408;
        uint32_t ah[4], al[4], bh[4], bl[4];
#pragma unroll
        for (int k = 0; k < 8; k++) {
            uint32_t ko = (uint32_t)k * 32;
            ldsm4(ah, aHi + ko);
            ldsm4(al, aLo + ko);
#pragma unroll
            for (int nb2 = 0; nb2 < 2; nb2++) {
                uint32_t bo = (uint32_t)nb2 * 16 * PB + ko;
                ldsm4(bh, whi + bo);
                ldsm4(bl, wlo + bo);
                mmabf(acc[nb2 * 2 + 0], ah, bh + 0);
                mmabf(acc[nb2 * 2 + 1], ah, bh + 2);
                mmabf(acc[nb2 * 2 + 0], ah, bl + 0);
                mmabf(acc[nb2 * 2 + 1], ah, bl + 2);
                mmabf(acc[nb2 * 2 + 0], al, bh + 0);
                mmabf(acc[nb2 * 2 + 1], al, bh + 2);
            }
        }
    }

    // ---- epilogue ----
    __syncthreads();
    lred[tid] = lsum;
    __syncthreads();

    int r0o = s * 16 + (lane >> 2);
    float l0 = (lred[r0o * 4 + 0] + lred[r0o * 4 + 1]) +
               (lred[r0o * 4 + 2] + lred[r0o * 4 + 3]);
    float l1 = (lred[(r0o + 8) * 4 + 0] + lred[(r0o + 8) * 4 + 1]) +
               (lred[(r0o + 8) * 4 + 2] + lred[(r0o + 8) * 4 + 3]);
    float inv0 = 1.0f / l0, inv1 = 1.0f / l1;
#pragma unroll
    for (int nb = 0; nb < 4; nb++) {
        int col = h * 32 + nb * 8 + (lane & 3) * 2;
        float v0 = acc[nb][0] * inv0, v1 = acc[nb][1] * inv0;
        float v2 = acc[nb][2] * inv1, v3 = acc[nb][3] * inv1;
        v0 = v0 > 0.f ? v0 : (__expf(v0) - 1.f);
        v1 = v1 > 0.f ? v1 : (__expf(v1) - 1.f);
        v2 = v2 > 0.f ? v2 : (__expf(v2) - 1.f);
        v3 = v3 > 0.f ? v3 : (__expf(v3) - 1.f);
        *(float2*)(out + (size_t)(i0 + r0o) * FOUT + col) = make_float2(v0, v1);
        *(float2*)(out + (size_t)(i0 + r0o + 8) * FOUT + col) = make_float2(v2, v3);
    }
}

// ---------------------------------------------------------------------------
extern "C" void kernel_launch(void* const* d_in, const int* in_sizes, int n_in,
                              void* d_out, int out_size) {
    const float* x   = (const float*)d_in[0];
    const int*   adj = (const int*)d_in[1];
    const float* W   = (const float*)d_in[2];
    const float* a   = (const float*)d_in[3];
    float* out = (float*)d_out;

    size_t smem_wh = (size_t)(32 * 132 + 128 * 64) * sizeof(float);
    static int attr_set = 0;
    if (!attr_set) {
        cudaFuncSetAttribute(wh_kernel, cudaFuncAttributeMaxDynamicSharedMemorySize,
                             (int)smem_wh);
        cudaFuncSetAttribute(attn_kernel, cudaFuncAttributeMaxDynamicSharedMemorySize,
                             SM_TOTB);
        attr_set = 1;
    }

    wh_kernel<<<NROWS / 32, 256, smem_wh>>>(x, W);
    wh12_kernel<<<NROWS / 8, 256>>>(a);
    tp_kernel<<<64, 256>>>();
    attn_kernel<<<NROWS / BI, 256, SM_TOTB>>>(adj, out);
}